// round 14
// baseline (speedup 1.0000x reference)
#include <cuda_runtime.h>
#include <math.h>
#include <stdint.h>

#define DAYS  365
#define NY    30
#define SGRID 4000
#define TT    (DAYS * NY)
#define NPAIR 435
#define NQ    5
#define K1_SER 16
#define SROW  397            // row stride; layout needs 368, sorted scratch 395
#define YPB   6              // years per block (pipelined)

#define POSINF __int_as_float(0x7f800000)
#define NEGINF __int_as_float(0xff800000)
#define FULLM  0xffffffffu

// ---------------- compile-time pair tables -----------------------------------
struct PairTab { int ij[NPAIR]; float inv[NPAIR]; };
static constexpr PairTab mk_tab() {
    PairTab t{};
    int p = 0;
    for (int i = 0; i < NY; i++)
        for (int j = i + 1; j < NY; j++, p++) {
            t.ij[p]  = i | (j << 8);
            t.inv[p] = 1.0f / (float)(j - i);
        }
    return t;
}
__device__ const PairTab g_tab = mk_tab();

// ---------------- accumulators (no allocations allowed) ----------------------
__device__ double g_sse;      // zero-init at load; reset by finalize each run
__device__ double g_trend;
__device__ int    g_done;

// ---------------- cp.async helpers -------------------------------------------
__device__ __forceinline__ uint32_t cvta_s(const void* p) {
    return (uint32_t)__cvta_generic_to_shared(p);
}
__device__ __forceinline__ void cp4(uint32_t saddr, const void* gptr) {
    asm volatile("cp.async.ca.shared.global [%0], [%1], 4;"
                 :: "r"(saddr), "l"(gptr));
}
__device__ __forceinline__ void cp_commit() {
    asm volatile("cp.async.commit_group;");
}
__device__ __forceinline__ void cp_wait1() {
    asm volatile("cp.async.wait_group 1;");
}
__device__ __forceinline__ void cp_wait0() {
    asm volatile("cp.async.wait_group 0;");
}

__device__ __forceinline__ void cswapF(float& a, float& b) {
    float lo = fminf(a, b), hi = fmaxf(a, b); a = lo; b = hi;
}

// Batcher odd-even merge sort of 8 (19 comparators, ascending)
__device__ __forceinline__ void sort8(float* v) {
    cswapF(v[0],v[1]); cswapF(v[2],v[3]); cswapF(v[0],v[2]); cswapF(v[1],v[3]);
    cswapF(v[1],v[2]);
    cswapF(v[4],v[5]); cswapF(v[6],v[7]); cswapF(v[4],v[6]); cswapF(v[5],v[7]);
    cswapF(v[5],v[6]);
    cswapF(v[0],v[4]); cswapF(v[1],v[5]); cswapF(v[2],v[6]); cswapF(v[3],v[7]);
    cswapF(v[2],v[4]); cswapF(v[3],v[5]);
    cswapF(v[1],v[2]); cswapF(v[3],v[4]); cswapF(v[5],v[6]);
}

// ============ pruned bitonic through k=256, 24 regs, TWO series/warp =========
// Slot g: {g0,g1,g2}->reg lo3, {g3..g6}->lane4, {g7,g8}->reg hi2 (hi2=3 virtual)
// Output: slots 0..255 (r0..15) ascending, slots 256..383 (r16..23) ascending.

__device__ __forceinline__ void P1(float v[24]) {
#pragma unroll
    for (int r = 0; r < 24; r++) if ((r & 1) == 0) cswapF(v[r], v[r | 1]);
}
__device__ __forceinline__ void P2(float v[24]) {
#pragma unroll
    for (int r = 0; r < 24; r++) if ((r & 2) == 0) cswapF(v[r], v[r | 2]);
}
__device__ __forceinline__ void P4(float v[24]) {
#pragma unroll
    for (int r = 0; r < 24; r++) if ((r & 4) == 0) cswapF(v[r], v[r | 4]);
}
__device__ __forceinline__ void P1h(float v[24]) {
#pragma unroll
    for (int r = 0; r < 16; r++) if ((r & 1) == 0) cswapF(v[r], v[r | 1]);
}
__device__ __forceinline__ void P2h(float v[24]) {
#pragma unroll
    for (int r = 0; r < 16; r++) if ((r & 2) == 0) cswapF(v[r], v[r | 2]);
}
__device__ __forceinline__ void P4h(float v[24]) {
#pragma unroll
    for (int r = 0; r < 16; r++) if ((r & 4) == 0) cswapF(v[r], v[r | 4]);
}
__device__ __forceinline__ void CR(float v[24], int lane, int lm) {
    bool kp = (lane & lm) == 0;
#pragma unroll
    for (int r = 0; r < 24; r++) {
        float o = __shfl_xor_sync(FULLM, v[r], lm);
        v[r] = kp ? fminf(v[r], o) : fmaxf(v[r], o);
    }
}
__device__ __forceinline__ void CRh(float v[24], int lane, int lm) {
    bool kp = (lane & lm) == 0;
#pragma unroll
    for (int r = 0; r < 16; r++) {
        float o = __shfl_xor_sync(FULLM, v[r], lm);
        v[r] = kp ? fminf(v[r], o) : fmaxf(v[r], o);
    }
}
__device__ __forceinline__ void FL(float v[24], int lane, int lmc, int pb) {
    bool kp = (lane & pb) == 0;
#pragma unroll
    for (int oct = 0; oct < 24; oct += 8) {
        float t[8];
#pragma unroll
        for (int i = 0; i < 8; i++) t[i] = __shfl_xor_sync(FULLM, v[oct + (i ^ 7)], lmc);
#pragma unroll
        for (int i = 0; i < 8; i++) v[oct + i] = kp ? fminf(v[oct + i], t[i])
                                                    : fmaxf(v[oct + i], t[i]);
    }
}
__device__ __forceinline__ void F256(float v[24]) {
#pragma unroll
    for (int h = 0; h < 2; h++) {
        int base = h ? 4 : 0;
        float t1[4], t2[4];
#pragma unroll
        for (int i = 0; i < 4; i++) {
            t1[i] = __shfl_xor_sync(FULLM, v[15 - (base + i)], 15);
            t2[i] = __shfl_xor_sync(FULLM, v[base + i], 15);
        }
#pragma unroll
        for (int i = 0; i < 4; i++) {
            v[base + i]        = fminf(v[base + i], t1[i]);
            v[15 - (base + i)] = fmaxf(v[15 - (base + i)], t2[i]);
        }
    }
}

__device__ __forceinline__ void bsort2runs(float v[24], int lane) {
    sort8(v); sort8(v + 8); sort8(v + 16);                   // k<=8
    FL(v, lane, 1, 1);  P4(v); P2(v); P1(v);                 // k=16
    FL(v, lane, 3, 2);  CR(v, lane, 1); P4(v); P2(v); P1(v); // k=32
    FL(v, lane, 7, 4);  CR(v, lane, 2); CR(v, lane, 1);
    P4(v); P2(v); P1(v);                                     // k=64
    FL(v, lane, 15, 8); CR(v, lane, 4); CR(v, lane, 2); CR(v, lane, 1);
    P4(v); P2(v); P1(v);                                     // k=128
    F256(v); CRh(v, lane, 8); CRh(v, lane, 4); CRh(v, lane, 2); CRh(v, lane, 1);
    P4h(v); P2h(v); P1h(v);                                  // k=256 (r<16)
}

// select rank k (1-based) from sorted A (m) + sorted B (n); slot g at
// base[g + (g>>5)], B at slots boff+g. 9 guarded bisection steps.
__device__ __forceinline__ float kth2(const float* base, int boff, int m, int n, int k) {
    int lo = max(0, k - n), hi = min(k, m);
#pragma unroll
    for (int it = 0; it < 9; it++) {
        int i  = (lo + hi + 1) >> 1;
        int ia = max(i - 1, 0);
        float Av = base[ia + (ia >> 5)];
        int j = k - i;
        int gb = boff + j;
        float Bv = (j < n) ? base[gb + (gb >> 5)] : POSINF;
        if (lo < hi) { if (Av <= Bv) lo = i; else hi = i - 1; }
    }
    int i = lo, j = k - lo;
    int ia = i - 1, jb = j - 1;
    float av = NEGINF, bv = NEGINF;
    if (i > 0) av = base[ia + (ia >> 5)];
    if (j > 0 && jb < n) { int gb = boff + jb; bv = base[gb + (gb >> 5)]; }
    return fmaxf(av, bv);
}

// ====== dual bitonic-to-2-runs for 512 slots, lane-major (k_theil) ===========
__device__ __forceinline__ void csw2(float& pa, float& pb, float& ta, float& tb) {
    cswapF(pa, pb); cswapF(ta, tb);
}
__device__ __forceinline__ void bsort2runs512_2(float p[16], float t[16], int lane) {
#pragma unroll
    for (int k = 2; k <= 16; k <<= 1) {
#pragma unroll
        for (int r = 0; r < 16; r++)
            if ((r & (k - 1)) < (k >> 1)) csw2(p[r],p[r^(k-1)],t[r],t[r^(k-1)]);
#pragma unroll
        for (int j = 8; j >= 1; j >>= 1)
            if (j <= (k >> 2)) {
#pragma unroll
                for (int r = 0; r < 16; r++)
                    if ((r & j) == 0) csw2(p[r],p[r|j],t[r],t[r|j]);
            }
    }
#pragma unroll
    for (int k = 32; k <= 256; k <<= 1) {
        {
            int  lm      = (k - 1) >> 4;
            bool keepmin = ((lane & (k >> 5)) == 0);
#pragma unroll
            for (int r = 0; r < 8; r++) {
                float aP = __shfl_xor_sync(FULLM, p[15 - r], lm);
                float bP = __shfl_xor_sync(FULLM, p[r], lm);
                float aT = __shfl_xor_sync(FULLM, t[15 - r], lm);
                float bT = __shfl_xor_sync(FULLM, t[r], lm);
                p[r]      = keepmin ? fminf(p[r], aP)      : fmaxf(p[r], aP);
                p[15 - r] = keepmin ? fminf(p[15 - r], bP) : fmaxf(p[15 - r], bP);
                t[r]      = keepmin ? fminf(t[r], aT)      : fmaxf(t[r], aT);
                t[15 - r] = keepmin ? fminf(t[15 - r], bT) : fmaxf(t[15 - r], bT);
            }
        }
#pragma unroll
        for (int j = 128; j >= 16; j >>= 1)
            if (j <= (k >> 2)) {
                int  lm      = j >> 4;
                bool keepmin = ((lane & lm) == 0);
#pragma unroll
                for (int r = 0; r < 16; r++) {
                    float oP = __shfl_xor_sync(FULLM, p[r], lm);
                    float oT = __shfl_xor_sync(FULLM, t[r], lm);
                    p[r] = keepmin ? fminf(p[r], oP) : fmaxf(p[r], oP);
                    t[r] = keepmin ? fminf(t[r], oT) : fmaxf(t[r], oT);
                }
            }
#pragma unroll
        for (int j = 8; j >= 1; j >>= 1)
            if (j <= (k >> 2)) {
#pragma unroll
                for (int r = 0; r < 16; r++)
                    if ((r & j) == 0) csw2(p[r],p[r|j],t[r],t[r|j]);
            }
    }
}

// ---------------- device outputs of kernel 1 ---------------------------------
__device__ float g_pM[SGRID * NY];
__device__ float g_tM[SGRID * NY];
__device__ float g_pQ[SGRID * NQ * NY];
__device__ float g_tQ[SGRID * NQ * NY];

// ---------------- kernel 1: pipelined transpose + SSE + sort + select --------
// grid (SGRID/16, NY/YPB), block 256 (8 warps; warp sorts 2 series per pass)
// dynamic smem: 2 buffers x {P,T} x [16][SROW] = 101,632 B -> 2 blocks/SM
__global__ __launch_bounds__(256, 2) void k_sortdays(const float* __restrict__ pred,
                                                     const float* __restrict__ obs) {
    extern __shared__ float dsm[];
    __shared__ float warpsum[8];

    int y0     = blockIdx.y * YPB;
    int s_base = blockIdx.x * K1_SER;
    int tid    = threadIdx.x;
    int w      = tid >> 5;
    int lane   = tid & 31;
    int lane4  = lane & 15;

    int sidx = 2 * w + (lane >> 4);     // this half-warp's series (0..15)
    int s    = s_base + sidx;

    // prefetch tile t into buffer t&1 (both arrays), one commit group
    auto prefetch = [&](int t) {
        int y = y0 + t;
        const float* pb = pred + (size_t)y * DAYS * SGRID + s_base;
        const float* tb = obs  + (size_t)y * DAYS * SGRID + s_base;
        float* bP = dsm + ((t & 1) * 2 + 0) * (K1_SER * SROW);
        float* bT = dsm + ((t & 1) * 2 + 1) * (K1_SER * SROW);
        for (int idx = tid; idx < DAYS * K1_SER; idx += 256) {
            int d  = idx >> 4;
            int sl = idx & 15;
            int ad = (d & 7) * 46 + (d >> 3);
            cp4(cvta_s(bP + sl * SROW + ad), pb + d * SGRID + sl);
            cp4(cvta_s(bT + sl * SROW + ad), tb + d * SGRID + sl);
        }
        cp_commit();
    };

    prefetch(0);

#pragma unroll 1
    for (int t = 0; t < YPB; t++) {
        bool more = (t + 1 < YPB);
        if (more) prefetch(t + 1);
        if (more) cp_wait1(); else cp_wait0();
        __syncthreads();

        int y = y0 + t;
        float* bP = dsm + ((t & 1) * 2 + 0) * (K1_SER * SROW);
        float* bT = dsm + ((t & 1) * 2 + 1) * (K1_SER * SROW);

        // SSE from smem (day-indexed: skip unwritten padding slots)
        float sse = 0.0f;
        for (int idx = tid; idx < DAYS * K1_SER; idx += 256) {
            int d  = idx >> 4;
            int sl = idx & 15;
            int ad = sl * SROW + (d & 7) * 46 + (d >> 3);
            float df = bP[ad] - bT[ad];
            sse += df * df;
        }
#pragma unroll
        for (int o = 16; o > 0; o >>= 1) sse += __shfl_down_sync(FULLM, sse, o);
        if (lane == 0) warpsum[w] = sse;
        __syncthreads();
        if (tid == 0) {
            float tot = 0.0f;
#pragma unroll
            for (int i = 0; i < 8; i++) tot += warpsum[i];
            atomicAdd(&g_sse, (double)tot);
        }

#pragma unroll 1
        for (int pass = 0; pass < 2; pass++) {
            float* row  = (pass ? bT : bP) + sidx * SROW;
            float* outM = pass ? g_tM : g_pM;
            float* outQ = pass ? g_tQ : g_pQ;

            // load: reg r holds slot g = (r&7) | (lane4<<3) | ((r>>3)<<7)
            float v[24];
            float msum = 0.0f;
#pragma unroll
            for (int r = 0; r < 24; r++) {
                int lo3 = r & 7, hi2 = r >> 3;
                int g   = lo3 | (lane4 << 3) | (hi2 << 7);
                if (g < DAYS) { v[r] = row[lo3 * 46 + lane4 + (hi2 << 4)]; msum += v[r]; }
                else          { v[r] = POSINF; }
            }
#pragma unroll
            for (int o = 8; o > 0; o >>= 1) msum += __shfl_xor_sync(FULLM, msum, o);
            if (lane4 == 0) outM[s * NY + y] = msum * (1.0f / (float)DAYS);

            bsort2runs(v, lane);

            // dump sorted runs: slot g -> row[g + (g>>5)]
#pragma unroll
            for (int r = 0; r < 24; r++) {
                int g = (r & 7) | (lane4 << 3) | ((r >> 3) << 7);
                row[g + (g >> 5)] = v[r];
            }
            __syncwarp();

            // lanes 0..4 of each half select one rank from A(256) + B(128)
            int R = lane4 == 0 ? 364 : lane4 == 1 ? 357 : lane4 == 2 ? 182
                  : lane4 == 3 ? 109 : 7;
            float ans = kth2(row, 256, 256, 128, R + 1);
            if (lane4 < NQ) outQ[(s * NQ + lane4) * NY + y] = ans;
            __syncwarp();
        }
        __syncthreads();   // all reads of this buffer done before its re-fill
    }
}

// ---------------- kernel 2: Theil-Sen medians + trend + fused finalize -------
// grid SGRID, block 192 (6 warps: warp0 = mean, warps 1..5 = quantiles)
__global__ __launch_bounds__(192, 5) void k_theil(float* __restrict__ out) {
    __shared__ float xs[6][2][NY];
    __shared__ float scr[6][2][528];    // 512 slots + (g>>5) padding

    int s    = blockIdx.x;
    int w    = threadIdx.x >> 5;
    int lane = threadIdx.x & 31;

    const float* xp;
    const float* xt;
    if (w == 0) { xp = g_pM + s * NY;                  xt = g_tM + s * NY; }
    else        { xp = g_pQ + (s * NQ + (w - 1)) * NY; xt = g_tQ + (s * NQ + (w - 1)) * NY; }
    if (lane < NY) {
        xs[w][0][lane] = xp[lane];
        xs[w][1][lane] = xt[lane];
    }
    __syncwarp();

    float vP[16], vT[16];
#pragma unroll
    for (int r = 0; r < 16; r++) {
        int p = (r << 5) | lane;   // arbitrary pair->slot map (median is set-invariant)
        if (p < NPAIR) {
            int   ij  = g_tab.ij[p];
            float inv = g_tab.inv[p];
            int i = ij & 255, j = ij >> 8;
            vP[r] = (xs[w][0][j] - xs[w][0][i]) * inv;
            vT[r] = (xs[w][1][j] - xs[w][1][i]) * inv;
        } else {
            vP[r] = POSINF;
            vT[r] = POSINF;
        }
    }

    bsort2runs512_2(vP, vT, lane);   // each: two sorted 256-runs

#pragma unroll
    for (int r = 0; r < 16; r++) {
        int g = (lane << 4) | r;
        int a = g + (g >> 5);
        scr[w][0][a] = vP[r];
        scr[w][1][a] = vT[r];
    }
    __syncwarp();

    // lane 0 selects median (rank 217, k=218) of P, lane 1 of T
    const float* base = (lane == 1) ? &scr[w][1][0] : &scr[w][0][0];
    float ans = kth2(base, 256, 256, 256, 218);
    float sp = __shfl_sync(FULLM, ans, 0);
    float st = __shfl_sync(FULLM, ans, 1);

    if (lane == 0) {
        double term;
        if (w == 0) { float d = st - sp;   term = (double)d * (double)d; }
        else        { float q = st / (-sp); term = (double)q * (double)q; }
        atomicAdd(&g_trend, term);
    }

    // last block finalizes output and resets accumulators for the next replay
    __syncthreads();
    if (threadIdx.x == 0) {
        __threadfence();
        if (atomicAdd(&g_done, 1) == (int)gridDim.x - 1) {
            double mse = g_sse / ((double)TT * (double)SGRID);
            out[0] = (float)(sqrt(mse) + g_trend / (double)SGRID);
            g_sse   = 0.0;
            g_trend = 0.0;
            g_done  = 0;
        }
    }
}

// ---------------- launch ------------------------------------------------------
extern "C" void kernel_launch(void* const* d_in, const int* in_sizes, int n_in,
                              void* d_out, int out_size) {
    const float* y_pred = (const float*)d_in[0];
    const float* y_obs  = (const float*)d_in[1];
    float* out = (float*)d_out;

    const int dyn = 4 * K1_SER * SROW * (int)sizeof(float);  // 101,632 B
    static int configured = 0;
    cudaFuncSetAttribute(k_sortdays, cudaFuncAttributeMaxDynamicSharedMemorySize, dyn);
    (void)configured;

    k_sortdays<<<dim3(SGRID / K1_SER, NY / YPB), 256, dyn>>>(y_pred, y_obs);
    k_theil<<<SGRID, 192>>>(out);
}

// round 15
// speedup vs baseline: 1.3049x; 1.3049x over previous
#include <cuda_runtime.h>
#include <math.h>
#include <stdint.h>

#define DAYS  365
#define NY    30
#define SGRID 4000
#define TT    (DAYS * NY)
#define NPAIR 435
#define NQ    5
#define K1_SER 16
#define SROW  397            // row stride; layout needs 368, sorted scratch 395

#define POSINF __int_as_float(0x7f800000)
#define NEGINF __int_as_float(0xff800000)
#define FULLM  0xffffffffu

// ---------------- compile-time pair tables -----------------------------------
struct PairTab { int ij[NPAIR]; float inv[NPAIR]; };
static constexpr PairTab mk_tab() {
    PairTab t{};
    int p = 0;
    for (int i = 0; i < NY; i++)
        for (int j = i + 1; j < NY; j++, p++) {
            t.ij[p]  = i | (j << 8);
            t.inv[p] = 1.0f / (float)(j - i);
        }
    return t;
}
__device__ const PairTab g_tab = mk_tab();

// ---------------- accumulators + intermediates (no allocations) --------------
__device__ double g_sse;      // zero at load; reset by fused finalize each run
__device__ double g_trend;
__device__ int    g_done;
__device__ float  g_pM[SGRID * NY];
__device__ float  g_tM[SGRID * NY];
__device__ float  g_pQ[SGRID * NQ * NY];
__device__ float  g_tQ[SGRID * NQ * NY];

__device__ __forceinline__ void cswapF(float& a, float& b) {
    float lo = fminf(a, b), hi = fmaxf(a, b); a = lo; b = hi;
}

// Batcher odd-even merge sort of 8 (19 comparators, ascending)
__device__ __forceinline__ void sort8(float* v) {
    cswapF(v[0],v[1]); cswapF(v[2],v[3]); cswapF(v[0],v[2]); cswapF(v[1],v[3]);
    cswapF(v[1],v[2]);
    cswapF(v[4],v[5]); cswapF(v[6],v[7]); cswapF(v[4],v[6]); cswapF(v[5],v[7]);
    cswapF(v[5],v[6]);
    cswapF(v[0],v[4]); cswapF(v[1],v[5]); cswapF(v[2],v[6]); cswapF(v[3],v[7]);
    cswapF(v[2],v[4]); cswapF(v[3],v[5]);
    cswapF(v[1],v[2]); cswapF(v[3],v[4]); cswapF(v[5],v[6]);
}

// ============ pruned bitonic through k=256, 24 regs, TWO series/warp =========
// Slot g: {g0,g1,g2}->reg lo3, {g3..g6}->lane4, {g7,g8}->reg hi2 (hi2=3 virtual)
// Output: slots 0..255 (r0..15) ascending, slots 256..383 (r16..23) ascending.

__device__ __forceinline__ void P1(float v[24]) {
#pragma unroll
    for (int r = 0; r < 24; r++) if ((r & 1) == 0) cswapF(v[r], v[r | 1]);
}
__device__ __forceinline__ void P2(float v[24]) {
#pragma unroll
    for (int r = 0; r < 24; r++) if ((r & 2) == 0) cswapF(v[r], v[r | 2]);
}
__device__ __forceinline__ void P4(float v[24]) {
#pragma unroll
    for (int r = 0; r < 24; r++) if ((r & 4) == 0) cswapF(v[r], v[r | 4]);
}
__device__ __forceinline__ void P1h(float v[24]) {
#pragma unroll
    for (int r = 0; r < 16; r++) if ((r & 1) == 0) cswapF(v[r], v[r | 1]);
}
__device__ __forceinline__ void P2h(float v[24]) {
#pragma unroll
    for (int r = 0; r < 16; r++) if ((r & 2) == 0) cswapF(v[r], v[r | 2]);
}
__device__ __forceinline__ void P4h(float v[24]) {
#pragma unroll
    for (int r = 0; r < 16; r++) if ((r & 4) == 0) cswapF(v[r], v[r | 4]);
}
__device__ __forceinline__ void CR(float v[24], int lane, int lm) {
    bool kp = (lane & lm) == 0;
#pragma unroll
    for (int r = 0; r < 24; r++) {
        float o = __shfl_xor_sync(FULLM, v[r], lm);
        v[r] = kp ? fminf(v[r], o) : fmaxf(v[r], o);
    }
}
__device__ __forceinline__ void CRh(float v[24], int lane, int lm) {
    bool kp = (lane & lm) == 0;
#pragma unroll
    for (int r = 0; r < 16; r++) {
        float o = __shfl_xor_sync(FULLM, v[r], lm);
        v[r] = kp ? fminf(v[r], o) : fmaxf(v[r], o);
    }
}
__device__ __forceinline__ void FL(float v[24], int lane, int lmc, int pb) {
    bool kp = (lane & pb) == 0;
#pragma unroll
    for (int oct = 0; oct < 24; oct += 8) {
        float t[8];
#pragma unroll
        for (int i = 0; i < 8; i++) t[i] = __shfl_xor_sync(FULLM, v[oct + (i ^ 7)], lmc);
#pragma unroll
        for (int i = 0; i < 8; i++) v[oct + i] = kp ? fminf(v[oct + i], t[i])
                                                    : fmaxf(v[oct + i], t[i]);
    }
}
__device__ __forceinline__ void F256(float v[24]) {
#pragma unroll
    for (int h = 0; h < 2; h++) {
        int base = h ? 4 : 0;
        float t1[4], t2[4];
#pragma unroll
        for (int i = 0; i < 4; i++) {
            t1[i] = __shfl_xor_sync(FULLM, v[15 - (base + i)], 15);
            t2[i] = __shfl_xor_sync(FULLM, v[base + i], 15);
        }
#pragma unroll
        for (int i = 0; i < 4; i++) {
            v[base + i]        = fminf(v[base + i], t1[i]);
            v[15 - (base + i)] = fmaxf(v[15 - (base + i)], t2[i]);
        }
    }
}

__device__ __forceinline__ void bsort2runs(float v[24], int lane) {
    sort8(v); sort8(v + 8); sort8(v + 16);                   // k<=8
    FL(v, lane, 1, 1);  P4(v); P2(v); P1(v);                 // k=16
    FL(v, lane, 3, 2);  CR(v, lane, 1); P4(v); P2(v); P1(v); // k=32
    FL(v, lane, 7, 4);  CR(v, lane, 2); CR(v, lane, 1);
    P4(v); P2(v); P1(v);                                     // k=64
    FL(v, lane, 15, 8); CR(v, lane, 4); CR(v, lane, 2); CR(v, lane, 1);
    P4(v); P2(v); P1(v);                                     // k=128
    F256(v); CRh(v, lane, 8); CRh(v, lane, 4); CRh(v, lane, 2); CRh(v, lane, 1);
    P4h(v); P2h(v); P1h(v);                                  // k=256 (r<16)
}

// select rank k (1-based) from sorted A (m) + sorted B (n); slot g at
// base[g + (g>>5)], B at slots boff+g. 9 guarded bisection steps.
__device__ __forceinline__ float kth2(const float* base, int boff, int m, int n, int k) {
    int lo = max(0, k - n), hi = min(k, m);
#pragma unroll
    for (int it = 0; it < 9; it++) {
        int i  = (lo + hi + 1) >> 1;
        int ia = max(i - 1, 0);
        float Av = base[ia + (ia >> 5)];
        int j = k - i;
        int gb = boff + j;
        float Bv = (j < n) ? base[gb + (gb >> 5)] : POSINF;
        if (lo < hi) { if (Av <= Bv) lo = i; else hi = i - 1; }
    }
    int i = lo, j = k - lo;
    int ia = i - 1, jb = j - 1;
    float av = NEGINF, bv = NEGINF;
    if (i > 0) av = base[ia + (ia >> 5)];
    if (j > 0 && jb < n) { int gb = boff + jb; bv = base[gb + (gb >> 5)]; }
    return fmaxf(av, bv);
}

// ====== dual bitonic-to-2-runs for 512 slots, lane-major (k_theil) ===========
__device__ __forceinline__ void csw2(float& pa, float& pb, float& ta, float& tb) {
    cswapF(pa, pb); cswapF(ta, tb);
}
__device__ __forceinline__ void bsort2runs512_2(float p[16], float t[16], int lane) {
#pragma unroll
    for (int k = 2; k <= 16; k <<= 1) {
#pragma unroll
        for (int r = 0; r < 16; r++)
            if ((r & (k - 1)) < (k >> 1)) csw2(p[r],p[r^(k-1)],t[r],t[r^(k-1)]);
#pragma unroll
        for (int j = 8; j >= 1; j >>= 1)
            if (j <= (k >> 2)) {
#pragma unroll
                for (int r = 0; r < 16; r++)
                    if ((r & j) == 0) csw2(p[r],p[r|j],t[r],t[r|j]);
            }
    }
#pragma unroll
    for (int k = 32; k <= 256; k <<= 1) {
        {
            int  lm      = (k - 1) >> 4;
            bool keepmin = ((lane & (k >> 5)) == 0);
#pragma unroll
            for (int r = 0; r < 8; r++) {
                float aP = __shfl_xor_sync(FULLM, p[15 - r], lm);
                float bP = __shfl_xor_sync(FULLM, p[r], lm);
                float aT = __shfl_xor_sync(FULLM, t[15 - r], lm);
                float bT = __shfl_xor_sync(FULLM, t[r], lm);
                p[r]      = keepmin ? fminf(p[r], aP)      : fmaxf(p[r], aP);
                p[15 - r] = keepmin ? fminf(p[15 - r], bP) : fmaxf(p[15 - r], bP);
                t[r]      = keepmin ? fminf(t[r], aT)      : fmaxf(t[r], aT);
                t[15 - r] = keepmin ? fminf(t[15 - r], bT) : fmaxf(t[15 - r], bT);
            }
        }
#pragma unroll
        for (int j = 128; j >= 16; j >>= 1)
            if (j <= (k >> 2)) {
                int  lm      = j >> 4;
                bool keepmin = ((lane & lm) == 0);
#pragma unroll
                for (int r = 0; r < 16; r++) {
                    float oP = __shfl_xor_sync(FULLM, p[r], lm);
                    float oT = __shfl_xor_sync(FULLM, t[r], lm);
                    p[r] = keepmin ? fminf(p[r], oP) : fmaxf(p[r], oP);
                    t[r] = keepmin ? fminf(t[r], oT) : fmaxf(t[r], oT);
                }
            }
#pragma unroll
        for (int j = 8; j >= 1; j >>= 1)
            if (j <= (k >> 2)) {
#pragma unroll
                for (int r = 0; r < 16; r++)
                    if ((r & j) == 0) csw2(p[r],p[r|j],t[r],t[r|j]);
            }
    }
}

// ---------------- kernel 1: transpose + SSE + sort-to-2-runs + select --------
// grid (SGRID/16, NY), block 256; dynamic smem 2*16*SROW*4 = 50,816 B (4/SM)
__global__ __launch_bounds__(256, 4) void k_sortdays(const float* __restrict__ pred,
                                                     const float* __restrict__ obs) {
    extern __shared__ float dsm[];
    float* shP = dsm;                       // [16][SROW]
    float* shT = dsm + K1_SER * SROW;
    __shared__ float warpsum[8];

    int y      = blockIdx.y;
    int s_base = blockIdx.x * K1_SER;
    int tid    = threadIdx.x;
    int w      = tid >> 5;
    int lane   = tid & 31;
    int lane4  = lane & 15;

    const float* pbase = pred + (size_t)y * DAYS * SGRID + s_base;
    const float* tbase = obs  + (size_t)y * DAYS * SGRID + s_base;

    // vectorized coalesced load + transpose (day d -> col (d&7)*46+(d>>3)) + SSE
    float sse = 0.0f;
    for (int idx = tid; idx < DAYS * 4; idx += 256) {
        int d  = idx >> 2;
        int q  = (idx & 3) << 2;
        int ad = (d & 7) * 46 + (d >> 3);
        float4 a4 = *(const float4*)(pbase + d * SGRID + q);
        float4 b4 = *(const float4*)(tbase + d * SGRID + q);
        shP[(q + 0) * SROW + ad] = a4.x;  shT[(q + 0) * SROW + ad] = b4.x;
        shP[(q + 1) * SROW + ad] = a4.y;  shT[(q + 1) * SROW + ad] = b4.y;
        shP[(q + 2) * SROW + ad] = a4.z;  shT[(q + 2) * SROW + ad] = b4.z;
        shP[(q + 3) * SROW + ad] = a4.w;  shT[(q + 3) * SROW + ad] = b4.w;
        float dx = a4.x - b4.x, dy = a4.y - b4.y;
        float dz = a4.z - b4.z, dw = a4.w - b4.w;
        sse += dx * dx + dy * dy + dz * dz + dw * dw;
    }
#pragma unroll
    for (int o = 16; o > 0; o >>= 1) sse += __shfl_down_sync(FULLM, sse, o);
    if (lane == 0) warpsum[w] = sse;
    __syncthreads();
    if (tid == 0) {
        float tot = 0.0f;
#pragma unroll
        for (int i = 0; i < 8; i++) tot += warpsum[i];
        atomicAdd(&g_sse, (double)tot);
    }

    int sidx = 2 * w + (lane >> 4);     // this half-warp's series (0..15)
    int s    = s_base + sidx;

#pragma unroll 1
    for (int pass = 0; pass < 2; pass++) {
        float* row  = (pass ? shT : shP) + sidx * SROW;
        float* outM = pass ? g_tM : g_pM;
        float* outQ = pass ? g_tQ : g_pQ;

        // load: reg r holds slot g = (r&7) | (lane4<<3) | ((r>>3)<<7)
        float v[24];
        float msum = 0.0f;
#pragma unroll
        for (int r = 0; r < 24; r++) {
            int lo3 = r & 7, hi2 = r >> 3;
            int g   = lo3 | (lane4 << 3) | (hi2 << 7);
            if (g < DAYS) { v[r] = row[lo3 * 46 + lane4 + (hi2 << 4)]; msum += v[r]; }
            else          { v[r] = POSINF; }
        }
#pragma unroll
        for (int o = 8; o > 0; o >>= 1) msum += __shfl_xor_sync(FULLM, msum, o);
        if (lane4 == 0) outM[s * NY + y] = msum * (1.0f / (float)DAYS);

        bsort2runs(v, lane);

        // dump sorted runs: slot g -> row[g + (g>>5)]  (conflict-free padding)
#pragma unroll
        for (int r = 0; r < 24; r++) {
            int g = (r & 7) | (lane4 << 3) | ((r >> 3) << 7);
            row[g + (g >> 5)] = v[r];
        }
        __syncwarp();

        // lanes 0..4 of each half select one rank from A(256) + B(128)
        int R = lane4 == 0 ? 364 : lane4 == 1 ? 357 : lane4 == 2 ? 182
              : lane4 == 3 ? 109 : 7;
        float ans = kth2(row, 256, 256, 128, R + 1);
        if (lane4 < NQ) outQ[(s * NQ + lane4) * NY + y] = ans;
        __syncwarp();
    }
}

// ---------------- kernel 2: Theil-Sen medians + trend + fused finalize -------
// grid SGRID, block 192 (6 warps: warp0 = mean, warps 1..5 = quantiles)
__global__ __launch_bounds__(192, 5) void k_theil(float* __restrict__ out) {
    __shared__ float xs[6][2][NY];
    __shared__ float scr[6][2][528];    // 512 slots + (g>>5) padding

    int s    = blockIdx.x;
    int w    = threadIdx.x >> 5;
    int lane = threadIdx.x & 31;

    const float* xp;
    const float* xt;
    if (w == 0) { xp = g_pM + s * NY;                  xt = g_tM + s * NY; }
    else        { xp = g_pQ + (s * NQ + (w - 1)) * NY; xt = g_tQ + (s * NQ + (w - 1)) * NY; }
    if (lane < NY) {
        xs[w][0][lane] = xp[lane];
        xs[w][1][lane] = xt[lane];
    }
    __syncwarp();

    float vP[16], vT[16];
#pragma unroll
    for (int r = 0; r < 16; r++) {
        int p = (r << 5) | lane;   // arbitrary pair->slot map (median is set-invariant)
        if (p < NPAIR) {
            int   ij  = g_tab.ij[p];
            float inv = g_tab.inv[p];
            int i = ij & 255, j = ij >> 8;
            vP[r] = (xs[w][0][j] - xs[w][0][i]) * inv;
            vT[r] = (xs[w][1][j] - xs[w][1][i]) * inv;
        } else {
            vP[r] = POSINF;
            vT[r] = POSINF;
        }
    }

    bsort2runs512_2(vP, vT, lane);   // each: two sorted 256-runs

#pragma unroll
    for (int r = 0; r < 16; r++) {
        int g = (lane << 4) | r;
        int a = g + (g >> 5);
        scr[w][0][a] = vP[r];
        scr[w][1][a] = vT[r];
    }
    __syncwarp();

    // lane 0 selects median (rank 217, k=218) of P, lane 1 of T
    const float* base = (lane == 1) ? &scr[w][1][0] : &scr[w][0][0];
    float ans = kth2(base, 256, 256, 256, 218);
    float sp = __shfl_sync(FULLM, ans, 0);
    float st = __shfl_sync(FULLM, ans, 1);

    if (lane == 0) {
        double term;
        if (w == 0) { float d = st - sp;   term = (double)d * (double)d; }
        else        { float q = st / (-sp); term = (double)q * (double)q; }
        atomicAdd(&g_trend, term);
    }

    // last block finalizes output and resets accumulators for the next replay
    __syncthreads();
    if (threadIdx.x == 0) {
        __threadfence();
        if (atomicAdd(&g_done, 1) == (int)gridDim.x - 1) {
            double mse = g_sse / ((double)TT * (double)SGRID);
            out[0] = (float)(sqrt(mse) + g_trend / (double)SGRID);
            g_sse   = 0.0;
            g_trend = 0.0;
            g_done  = 0;
        }
    }
}

// ---------------- launch ------------------------------------------------------
extern "C" void kernel_launch(void* const* d_in, const int* in_sizes, int n_in,
                              void* d_out, int out_size) {
    const float* y_pred = (const float*)d_in[0];
    const float* y_obs  = (const float*)d_in[1];
    float* out = (float*)d_out;

    const int dyn = 2 * K1_SER * SROW * (int)sizeof(float);  // 50,816 B
    cudaFuncSetAttribute(k_sortdays, cudaFuncAttributeMaxDynamicSharedMemorySize, dyn);

    k_sortdays<<<dim3(SGRID / K1_SER, NY), 256, dyn>>>(y_pred, y_obs);
    k_theil<<<SGRID, 192>>>(out);
}

// round 16
// speedup vs baseline: 1.3746x; 1.0535x over previous
#include <cuda_runtime.h>
#include <math.h>
#include <stdint.h>

#define DAYS  365
#define NY    30
#define SGRID 4000
#define TT    (DAYS * NY)
#define NPAIR 435
#define NQ    5
#define K1_SER 16
#define SROW  397            // row stride; layout needs 368, sorted scratch 395

#define POSINF __int_as_float(0x7f800000)
#define NEGINF __int_as_float(0xff800000)
#define FULLM  0xffffffffu

// ---------------- compile-time pair tables -----------------------------------
struct PairTab { int ij[NPAIR]; float inv[NPAIR]; };
static constexpr PairTab mk_tab() {
    PairTab t{};
    int p = 0;
    for (int i = 0; i < NY; i++)
        for (int j = i + 1; j < NY; j++, p++) {
            t.ij[p]  = i | (j << 8);
            t.inv[p] = 1.0f / (float)(j - i);
        }
    return t;
}
__device__ const PairTab g_tab = mk_tab();

// ---------------- accumulators + intermediates (no allocations) --------------
__device__ double g_sse;      // zero at load; reset by fused finalize each run
__device__ double g_trend;
__device__ int    g_done;
__device__ float  g_pM[SGRID * NY];
__device__ float  g_tM[SGRID * NY];
__device__ float  g_pQ[SGRID * NQ * NY];
__device__ float  g_tQ[SGRID * NQ * NY];

__device__ __forceinline__ void cswapF(float& a, float& b) {
    float lo = fminf(a, b), hi = fmaxf(a, b); a = lo; b = hi;
}

// Batcher odd-even merge sort of 8 (19 comparators, ascending)
__device__ __forceinline__ void sort8(float* v) {
    cswapF(v[0],v[1]); cswapF(v[2],v[3]); cswapF(v[0],v[2]); cswapF(v[1],v[3]);
    cswapF(v[1],v[2]);
    cswapF(v[4],v[5]); cswapF(v[6],v[7]); cswapF(v[4],v[6]); cswapF(v[5],v[7]);
    cswapF(v[5],v[6]);
    cswapF(v[0],v[4]); cswapF(v[1],v[5]); cswapF(v[2],v[6]); cswapF(v[3],v[7]);
    cswapF(v[2],v[4]); cswapF(v[3],v[5]);
    cswapF(v[1],v[2]); cswapF(v[3],v[4]); cswapF(v[5],v[6]);
}

// ============ pruned bitonic through k=256, 24 regs, TWO series/warp =========
// Slot g: {g0,g1,g2}->reg lo3, {g3..g6}->lane4, {g7,g8}->reg hi2 (hi2=3 virtual)
// Output: slots 0..255 (r0..15) ascending, slots 256..383 (r16..23) ascending.

__device__ __forceinline__ void P1(float v[24]) {
#pragma unroll
    for (int r = 0; r < 24; r++) if ((r & 1) == 0) cswapF(v[r], v[r | 1]);
}
__device__ __forceinline__ void P2(float v[24]) {
#pragma unroll
    for (int r = 0; r < 24; r++) if ((r & 2) == 0) cswapF(v[r], v[r | 2]);
}
__device__ __forceinline__ void P4(float v[24]) {
#pragma unroll
    for (int r = 0; r < 24; r++) if ((r & 4) == 0) cswapF(v[r], v[r | 4]);
}
__device__ __forceinline__ void P1h(float v[24]) {
#pragma unroll
    for (int r = 0; r < 16; r++) if ((r & 1) == 0) cswapF(v[r], v[r | 1]);
}
__device__ __forceinline__ void P2h(float v[24]) {
#pragma unroll
    for (int r = 0; r < 16; r++) if ((r & 2) == 0) cswapF(v[r], v[r | 2]);
}
__device__ __forceinline__ void P4h(float v[24]) {
#pragma unroll
    for (int r = 0; r < 16; r++) if ((r & 4) == 0) cswapF(v[r], v[r | 4]);
}
__device__ __forceinline__ void CR(float v[24], int lane, int lm) {
    bool kp = (lane & lm) == 0;
#pragma unroll
    for (int r = 0; r < 24; r++) {
        float o = __shfl_xor_sync(FULLM, v[r], lm);
        v[r] = kp ? fminf(v[r], o) : fmaxf(v[r], o);
    }
}
__device__ __forceinline__ void CRh(float v[24], int lane, int lm) {
    bool kp = (lane & lm) == 0;
#pragma unroll
    for (int r = 0; r < 16; r++) {
        float o = __shfl_xor_sync(FULLM, v[r], lm);
        v[r] = kp ? fminf(v[r], o) : fmaxf(v[r], o);
    }
}
__device__ __forceinline__ void FL(float v[24], int lane, int lmc, int pb) {
    bool kp = (lane & pb) == 0;
#pragma unroll
    for (int oct = 0; oct < 24; oct += 8) {
        float t[8];
#pragma unroll
        for (int i = 0; i < 8; i++) t[i] = __shfl_xor_sync(FULLM, v[oct + (i ^ 7)], lmc);
#pragma unroll
        for (int i = 0; i < 8; i++) v[oct + i] = kp ? fminf(v[oct + i], t[i])
                                                    : fmaxf(v[oct + i], t[i]);
    }
}
__device__ __forceinline__ void F256(float v[24]) {
#pragma unroll
    for (int h = 0; h < 2; h++) {
        int base = h ? 4 : 0;
        float t1[4], t2[4];
#pragma unroll
        for (int i = 0; i < 4; i++) {
            t1[i] = __shfl_xor_sync(FULLM, v[15 - (base + i)], 15);
            t2[i] = __shfl_xor_sync(FULLM, v[base + i], 15);
        }
#pragma unroll
        for (int i = 0; i < 4; i++) {
            v[base + i]        = fminf(v[base + i], t1[i]);
            v[15 - (base + i)] = fmaxf(v[15 - (base + i)], t2[i]);
        }
    }
}

__device__ __forceinline__ void bsort2runs(float v[24], int lane) {
    sort8(v); sort8(v + 8); sort8(v + 16);                   // k<=8
    FL(v, lane, 1, 1);  P4(v); P2(v); P1(v);                 // k=16
    FL(v, lane, 3, 2);  CR(v, lane, 1); P4(v); P2(v); P1(v); // k=32
    FL(v, lane, 7, 4);  CR(v, lane, 2); CR(v, lane, 1);
    P4(v); P2(v); P1(v);                                     // k=64
    FL(v, lane, 15, 8); CR(v, lane, 4); CR(v, lane, 2); CR(v, lane, 1);
    P4(v); P2(v); P1(v);                                     // k=128
    F256(v); CRh(v, lane, 8); CRh(v, lane, 4); CRh(v, lane, 2); CRh(v, lane, 1);
    P4h(v); P2h(v); P1h(v);                                  // k=256 (r<16)
}

// select rank k (1-based) from sorted A (m) + sorted B (n); slot g at
// base[g + (g>>5)], B at slots boff+g. IT guarded bisection steps
// (IT must satisfy 2^IT >= initial interval length + 1).
template <int IT>
__device__ __forceinline__ float kth2(const float* base, int boff, int m, int n, int k) {
    int lo = max(0, k - n), hi = min(k, m);
#pragma unroll
    for (int it = 0; it < IT; it++) {
        int i  = (lo + hi + 1) >> 1;
        int ia = max(i - 1, 0);
        float Av = base[ia + (ia >> 5)];
        int j = k - i;
        int gb = boff + j;
        float Bv = (j < n) ? base[gb + (gb >> 5)] : POSINF;
        if (lo < hi) { if (Av <= Bv) lo = i; else hi = i - 1; }
    }
    int i = lo, j = k - lo;
    int ia = i - 1, jb = j - 1;
    float av = NEGINF, bv = NEGINF;
    if (i > 0) av = base[ia + (ia >> 5)];
    if (j > 0 && jb < n) { int gb = boff + jb; bv = base[gb + (gb >> 5)]; }
    return fmaxf(av, bv);
}

// ====== dual bitonic-to-2-runs for 512 slots, lane-major (k_theil) ===========
__device__ __forceinline__ void csw2(float& pa, float& pb, float& ta, float& tb) {
    cswapF(pa, pb); cswapF(ta, tb);
}
__device__ __forceinline__ void bsort2runs512_2(float p[16], float t[16], int lane) {
#pragma unroll
    for (int k = 2; k <= 16; k <<= 1) {
#pragma unroll
        for (int r = 0; r < 16; r++)
            if ((r & (k - 1)) < (k >> 1)) csw2(p[r],p[r^(k-1)],t[r],t[r^(k-1)]);
#pragma unroll
        for (int j = 8; j >= 1; j >>= 1)
            if (j <= (k >> 2)) {
#pragma unroll
                for (int r = 0; r < 16; r++)
                    if ((r & j) == 0) csw2(p[r],p[r|j],t[r],t[r|j]);
            }
    }
#pragma unroll
    for (int k = 32; k <= 256; k <<= 1) {
        {
            int  lm      = (k - 1) >> 4;
            bool keepmin = ((lane & (k >> 5)) == 0);
#pragma unroll
            for (int r = 0; r < 8; r++) {
                float aP = __shfl_xor_sync(FULLM, p[15 - r], lm);
                float bP = __shfl_xor_sync(FULLM, p[r], lm);
                float aT = __shfl_xor_sync(FULLM, t[15 - r], lm);
                float bT = __shfl_xor_sync(FULLM, t[r], lm);
                p[r]      = keepmin ? fminf(p[r], aP)      : fmaxf(p[r], aP);
                p[15 - r] = keepmin ? fminf(p[15 - r], bP) : fmaxf(p[15 - r], bP);
                t[r]      = keepmin ? fminf(t[r], aT)      : fmaxf(t[r], aT);
                t[15 - r] = keepmin ? fminf(t[15 - r], bT) : fmaxf(t[15 - r], bT);
            }
        }
#pragma unroll
        for (int j = 128; j >= 16; j >>= 1)
            if (j <= (k >> 2)) {
                int  lm      = j >> 4;
                bool keepmin = ((lane & lm) == 0);
#pragma unroll
                for (int r = 0; r < 16; r++) {
                    float oP = __shfl_xor_sync(FULLM, p[r], lm);
                    float oT = __shfl_xor_sync(FULLM, t[r], lm);
                    p[r] = keepmin ? fminf(p[r], oP) : fmaxf(p[r], oP);
                    t[r] = keepmin ? fminf(t[r], oT) : fmaxf(t[r], oT);
                }
            }
#pragma unroll
        for (int j = 8; j >= 1; j >>= 1)
            if (j <= (k >> 2)) {
#pragma unroll
                for (int r = 0; r < 16; r++)
                    if ((r & j) == 0) csw2(p[r],p[r|j],t[r],t[r|j]);
            }
    }
}

// ---------------- kernel 1: transpose + SSE + sort-to-2-runs + select --------
// grid (SGRID/16, NY), block 256; dynamic smem 2*16*SROW*4 = 50,816 B (4/SM)
__global__ __launch_bounds__(256, 4) void k_sortdays(const float* __restrict__ pred,
                                                     const float* __restrict__ obs) {
    extern __shared__ float dsm[];
    float* shP = dsm;                       // [16][SROW]
    float* shT = dsm + K1_SER * SROW;
    __shared__ float warpsum[8];

    int y      = blockIdx.y;
    int s_base = blockIdx.x * K1_SER;
    int tid    = threadIdx.x;
    int w      = tid >> 5;
    int lane   = tid & 31;
    int lane4  = lane & 15;

    const float* pbase = pred + (size_t)y * DAYS * SGRID + s_base;
    const float* tbase = obs  + (size_t)y * DAYS * SGRID + s_base;

    // vectorized coalesced load + transpose (day d -> col (d&7)*46+(d>>3)) + SSE
    float sse = 0.0f;
    for (int idx = tid; idx < DAYS * 4; idx += 256) {
        int d  = idx >> 2;
        int q  = (idx & 3) << 2;
        int ad = (d & 7) * 46 + (d >> 3);
        float4 a4 = *(const float4*)(pbase + d * SGRID + q);
        float4 b4 = *(const float4*)(tbase + d * SGRID + q);
        shP[(q + 0) * SROW + ad] = a4.x;  shT[(q + 0) * SROW + ad] = b4.x;
        shP[(q + 1) * SROW + ad] = a4.y;  shT[(q + 1) * SROW + ad] = b4.y;
        shP[(q + 2) * SROW + ad] = a4.z;  shT[(q + 2) * SROW + ad] = b4.z;
        shP[(q + 3) * SROW + ad] = a4.w;  shT[(q + 3) * SROW + ad] = b4.w;
        float dx = a4.x - b4.x, dy = a4.y - b4.y;
        float dz = a4.z - b4.z, dw = a4.w - b4.w;
        sse += dx * dx + dy * dy + dz * dz + dw * dw;
    }
#pragma unroll
    for (int o = 16; o > 0; o >>= 1) sse += __shfl_down_sync(FULLM, sse, o);
    if (lane == 0) warpsum[w] = sse;
    __syncthreads();
    if (tid == 0) {
        float tot = 0.0f;
#pragma unroll
        for (int i = 0; i < 8; i++) tot += warpsum[i];
        atomicAdd(&g_sse, (double)tot);
    }

    int sidx = 2 * w + (lane >> 4);     // this half-warp's series (0..15)
    int s    = s_base + sidx;
    float* rowP = shP + sidx * SROW;
    float* rowT = shT + sidx * SROW;

    // pass loop: sort + dump only (searches are merged afterwards)
#pragma unroll 1
    for (int pass = 0; pass < 2; pass++) {
        float* row  = pass ? rowT : rowP;
        float* outM = pass ? g_tM : g_pM;

        // load: reg r holds slot g = (r&7) | (lane4<<3) | ((r>>3)<<7)
        float v[24];
        float msum = 0.0f;
#pragma unroll
        for (int r = 0; r < 24; r++) {
            int lo3 = r & 7, hi2 = r >> 3;
            int g   = lo3 | (lane4 << 3) | (hi2 << 7);
            if (g < DAYS) { v[r] = row[lo3 * 46 + lane4 + (hi2 << 4)]; msum += v[r]; }
            else          { v[r] = POSINF; }
        }
#pragma unroll
        for (int o = 8; o > 0; o >>= 1) msum += __shfl_xor_sync(FULLM, msum, o);
        if (lane4 == 0) outM[s * NY + y] = msum * (1.0f / (float)DAYS);

        bsort2runs(v, lane);

        // dump sorted runs: slot g -> row[g + (g>>5)]  (conflict-free padding)
#pragma unroll
        for (int r = 0; r < 24; r++) {
            int g = (r & 7) | (lane4 << 3) | ((r >> 3) << 7);
            row[g + (g >> 5)] = v[r];
        }
    }
    __syncwarp();

    // merged search: lanes 0..4 -> P ranks, lanes 5..9 -> T ranks.
    // k1 interval lengths <= 110, so 7 bisection steps suffice (2^7=128).
    int rq = (lane4 < NQ) ? lane4 : lane4 - NQ;
    int R  = rq == 0 ? 364 : rq == 1 ? 357 : rq == 2 ? 182 : rq == 3 ? 109 : 7;
    const float* base = (lane4 < NQ) ? rowP : rowT;
    float ans = kth2<7>(base, 256, 256, 128, R + 1);
    if (lane4 < NQ)          g_pQ[(s * NQ + rq) * NY + y] = ans;
    else if (lane4 < 2 * NQ) g_tQ[(s * NQ + rq) * NY + y] = ans;
}

// ---------------- kernel 2: Theil-Sen medians + trend + fused finalize -------
// grid SGRID, block 192 (6 warps: warp0 = mean, warps 1..5 = quantiles)
__global__ __launch_bounds__(192, 5) void k_theil(float* __restrict__ out) {
    __shared__ float xs[6][2][NY];
    __shared__ float scr[6][2][528];    // 512 slots + (g>>5) padding

    int s    = blockIdx.x;
    int w    = threadIdx.x >> 5;
    int lane = threadIdx.x & 31;

    const float* xp;
    const float* xt;
    if (w == 0) { xp = g_pM + s * NY;                  xt = g_tM + s * NY; }
    else        { xp = g_pQ + (s * NQ + (w - 1)) * NY; xt = g_tQ + (s * NQ + (w - 1)) * NY; }
    if (lane < NY) {
        xs[w][0][lane] = xp[lane];
        xs[w][1][lane] = xt[lane];
    }
    __syncwarp();

    float vP[16], vT[16];
#pragma unroll
    for (int r = 0; r < 16; r++) {
        int p = (r << 5) | lane;   // arbitrary pair->slot map (median is set-invariant)
        if (p < NPAIR) {
            int   ij  = g_tab.ij[p];
            float inv = g_tab.inv[p];
            int i = ij & 255, j = ij >> 8;
            vP[r] = (xs[w][0][j] - xs[w][0][i]) * inv;
            vT[r] = (xs[w][1][j] - xs[w][1][i]) * inv;
        } else {
            vP[r] = POSINF;
            vT[r] = POSINF;
        }
    }

    bsort2runs512_2(vP, vT, lane);   // each: two sorted 256-runs

#pragma unroll
    for (int r = 0; r < 16; r++) {
        int g = (lane << 4) | r;
        int a = g + (g >> 5);
        scr[w][0][a] = vP[r];
        scr[w][1][a] = vT[r];
    }
    __syncwarp();

    // lane 0 selects median (rank 217, k=218) of P, lane 1 of T (len 218 -> 8 steps)
    const float* base = (lane == 1) ? &scr[w][1][0] : &scr[w][0][0];
    float ans = kth2<8>(base, 256, 256, 256, 218);
    float sp = __shfl_sync(FULLM, ans, 0);
    float st = __shfl_sync(FULLM, ans, 1);

    if (lane == 0) {
        double term;
        if (w == 0) { float d = st - sp;   term = (double)d * (double)d; }
        else        { float q = st / (-sp); term = (double)q * (double)q; }
        atomicAdd(&g_trend, term);
    }

    // last block finalizes output and resets accumulators for the next replay
    __syncthreads();
    if (threadIdx.x == 0) {
        __threadfence();
        if (atomicAdd(&g_done, 1) == (int)gridDim.x - 1) {
            double mse = g_sse / ((double)TT * (double)SGRID);
            out[0] = (float)(sqrt(mse) + g_trend / (double)SGRID);
            g_sse   = 0.0;
            g_trend = 0.0;
            g_done  = 0;
        }
    }
}

// ---------------- launch ------------------------------------------------------
extern "C" void kernel_launch(void* const* d_in, const int* in_sizes, int n_in,
                              void* d_out, int out_size) {
    const float* y_pred = (const float*)d_in[0];
    const float* y_obs  = (const float*)d_in[1];
    float* out = (float*)d_out;

    const int dyn = 2 * K1_SER * SROW * (int)sizeof(float);  // 50,816 B
    cudaFuncSetAttribute(k_sortdays, cudaFuncAttributeMaxDynamicSharedMemorySize, dyn);

    k_sortdays<<<dim3(SGRID / K1_SER, NY), 256, dyn>>>(y_pred, y_obs);
    k_theil<<<SGRID, 192>>>(out);
}